// round 4
// baseline (speedup 1.0000x reference)
#include <cuda_runtime.h>
#include <cuda_bf16.h>
#include <cstdint>

// ---------------- problem constants ----------------
#define NROWS 8192
#define DDIM  768

// ---------------- GEMM tiling ----------------
#define BM 64              // ex rows per m-block (A resident)
#define BN 256             // ey rows per tile
#define BK 64              // k per pipeline chunk
#define NKT (DDIM / BK)    // 12 k-chunks per tile
#define NNT (NROWS / BN)   // 32 n-tiles per m-block
#define NMB (NROWS / BM)   // 128 m-blocks
#define TOTAL_TILES (NMB * NNT)  // 4096
#define NCTA 152           // GB300: 152 SMs, one wave

// smem layout
#define A_STRIDE_B 1552                 // (768+8) bf16 -> conflict-free ldsm
#define OFF_A 0
#define A_BYTES (BM * A_STRIDE_B)       // 99328
#define B_ROW_B 144                     // (64+8) bf16 per row
#define B_STAGE_B (BN * B_ROW_B)        // 36864
#define OFF_B A_BYTES
#define OFF_RED (OFF_B + 3 * B_STAGE_B) // 209920
#define SMEM_TOTAL (OFF_RED + 4 * BM * 4)

// ---------------- device scratch ----------------
__device__ __nv_bfloat16 g_exn[NROWS * DDIM];
__device__ __nv_bfloat16 g_eyn[NROWS * DDIM];

// ---------------- PTX helpers ----------------
__device__ __forceinline__ uint32_t s2u(const void* p) {
    uint32_t a;
    asm("{ .reg .u64 t; cvta.to.shared.u64 t, %1; cvt.u32.u64 %0, t; }" : "=r"(a) : "l"(p));
    return a;
}
__device__ __forceinline__ void cpa16(uint32_t dst, const void* src) {
    asm volatile("cp.async.cg.shared.global [%0], [%1], 16;" :: "r"(dst), "l"(src));
}
__device__ __forceinline__ void cpa_commit() { asm volatile("cp.async.commit_group;"); }
__device__ __forceinline__ void cpa_wait0()  { asm volatile("cp.async.wait_group 0;"); }
__device__ __forceinline__ void cpa_wait1()  { asm volatile("cp.async.wait_group 1;"); }
__device__ __forceinline__ void ldsm4(uint32_t (&r)[4], uint32_t addr) {
    asm volatile("ldmatrix.sync.aligned.m8n8.x4.shared.b16 {%0,%1,%2,%3}, [%4];"
                 : "=r"(r[0]), "=r"(r[1]), "=r"(r[2]), "=r"(r[3]) : "r"(addr));
}
__device__ __forceinline__ void mma16816(float (&c)[4], const uint32_t (&a)[4],
                                         uint32_t b0, uint32_t b1) {
    asm volatile(
        "mma.sync.aligned.m16n8k16.row.col.f32.bf16.bf16.f32 "
        "{%0,%1,%2,%3}, {%4,%5,%6,%7}, {%8,%9}, {%0,%1,%2,%3};"
        : "+f"(c[0]), "+f"(c[1]), "+f"(c[2]), "+f"(c[3])
        : "r"(a[0]), "r"(a[1]), "r"(a[2]), "r"(a[3]), "r"(b0), "r"(b1));
}

// ---------------------------------------------------------------------------
// out init (poisoned by harness; atomics need 0.0f start)
// ---------------------------------------------------------------------------
__global__ void init_out_kernel(float* __restrict__ out) {
    out[blockIdx.x * 256 + threadIdx.x] = 0.0f;
}

// ---------------------------------------------------------------------------
// Row L2-normalize fp32 -> bf16, warp-per-row (ref: norm = max(||x||,1e-8))
// ---------------------------------------------------------------------------
__global__ __launch_bounds__(256) void normalize_kernel(const float* __restrict__ in, int sel) {
    __nv_bfloat16* outg = sel ? g_eyn : g_exn;
    const int w = threadIdx.x >> 5;
    const int lane = threadIdx.x & 31;
    const int row = blockIdx.x * 8 + w;

    const float4* p = (const float4*)(in + (size_t)row * DDIM);
    float4 v[6];
    float s = 0.f;
#pragma unroll
    for (int j = 0; j < 6; j++) {
        v[j] = p[lane + j * 32];
        s += v[j].x * v[j].x + v[j].y * v[j].y + v[j].z * v[j].z + v[j].w * v[j].w;
    }
#pragma unroll
    for (int o = 16; o; o >>= 1) s += __shfl_xor_sync(0xffffffffu, s, o);
    const float inv = 1.0f / fmaxf(sqrtf(s), 1e-8f);

    uint4* q = (uint4*)(outg + (size_t)row * DDIM);
#pragma unroll
    for (int j = 0; j < 3; j++) {
        const float4 a = v[2 * j], b = v[2 * j + 1];
        uint4 o;
        o.x = __uint_as_float(0), o.y = 0, o.z = 0, o.w = 0; // placate init
        __nv_bfloat162 p0 = __floats2bfloat162_rn(a.x * inv, a.y * inv);
        __nv_bfloat162 p1 = __floats2bfloat162_rn(a.z * inv, a.w * inv);
        __nv_bfloat162 p2 = __floats2bfloat162_rn(b.x * inv, b.y * inv);
        __nv_bfloat162 p3 = __floats2bfloat162_rn(b.z * inv, b.w * inv);
        o.x = *(uint32_t*)&p0; o.y = *(uint32_t*)&p1;
        o.z = *(uint32_t*)&p2; o.w = *(uint32_t*)&p3;
        // interleave: float4 pair j covers bf16 elements [8j*... ] lane-major
        q[lane + j * 32 + 0] = o;
    }
}

// ---------------------------------------------------------------------------
// Persistent fused GEMM + row-max. 152 CTAs over 4096 (m,nt) tiles.
// ---------------------------------------------------------------------------
__global__ __launch_bounds__(256, 1) void chamfer_kernel(float* __restrict__ out) {
    extern __shared__ char smem[];
    const uint32_t sb = s2u(smem);
    float* red = (float*)(smem + OFF_RED);

    const int tid = threadIdx.x;
    const int lane = tid & 31;
    const int wid = tid >> 5;
    const int wm = wid >> 2;
    const int wn = wid & 3;
    const int g = lane >> 2;
    const int tig = lane & 3;

    const int t0 = (int)(((long long)blockIdx.x * TOTAL_TILES) / NCTA);
    const int t1 = (int)(((long long)(blockIdx.x + 1) * TOTAL_TILES) / NCTA);

    // B chunk loader: 256 rows, each thread owns 1 row (8 x 16B)
    auto issueB = [&](int segTile, int c) {
        const int tile = segTile + c / NKT;
        const int nt = tile & (NNT - 1);
        const int kt = c % NKT;
        const __nv_bfloat16* src = g_eyn + (size_t)nt * BN * DDIM + (size_t)tid * DDIM + kt * BK;
        const uint32_t dst = sb + OFF_B + (c % 3) * B_STAGE_B + tid * B_ROW_B;
#pragma unroll
        for (int j = 0; j < 8; j++) cpa16(dst + j * 16, src + j * 8);
    };

    const int lrow = lane & 15;
    const int koff = (lane >> 4) * 16;
    const uint32_t aAddr0 = sb + OFF_A + (wm * 32 + lrow) * A_STRIDE_B + koff;
    const uint32_t bAddr0 = sb + OFF_B + (wn * 64 + lrow) * B_ROW_B + koff;

    int t = t0;
    while (t < t1) {
        const int m = t >> 5;                       // m-block
        const int segEnd = min((m + 1) << 5, t1);   // segment = same-m tiles
        const int ntiles = segEnd - t;
        const int nch = ntiles * NKT;

        // load resident A for this m-block (group 1)
        const __nv_bfloat16* Ag = g_exn + (size_t)m * BM * DDIM;
        for (int idx = tid; idx < BM * 96; idx += 256) {
            const int row = idx / 96, c = idx % 96;
            cpa16(sb + OFF_A + row * A_STRIDE_B + c * 16, Ag + (size_t)row * DDIM + c * 8);
        }
        cpa_commit();
        issueB(t, 0); cpa_commit();
        issueB(t, 1); cpa_commit();

        float runmax[2][2];
#pragma unroll
        for (int i = 0; i < 2; i++)
#pragma unroll
            for (int j = 0; j < 2; j++) runmax[i][j] = -1e30f;

        int c = 0;
        for (int lt = 0; lt < ntiles; ++lt) {
            float acc[2][8][4];
#pragma unroll
            for (int mt = 0; mt < 2; mt++)
#pragma unroll
                for (int n8 = 0; n8 < 8; n8++)
#pragma unroll
                    for (int r = 0; r < 4; r++) acc[mt][n8][r] = 0.f;

            for (int kt = 0; kt < NKT; ++kt, ++c) {
                if (c == nch - 1) cpa_wait0(); else cpa_wait1();
                __syncthreads();
                if (c + 2 < nch) { issueB(t, c + 2); cpa_commit(); }

                const uint32_t bStage = bAddr0 + (c % 3) * B_STAGE_B;
                const uint32_t aK = aAddr0 + kt * (BK * 2);
#pragma unroll
                for (int kk = 0; kk < 4; ++kk) {
                    uint32_t a[2][4], b[4][4];
#pragma unroll
                    for (int mt = 0; mt < 2; mt++)
                        ldsm4(a[mt], aK + mt * 16 * A_STRIDE_B + kk * 32);
#pragma unroll
                    for (int n16 = 0; n16 < 4; n16++)
                        ldsm4(b[n16], bStage + n16 * 16 * B_ROW_B + kk * 32);
#pragma unroll
                    for (int mt = 0; mt < 2; mt++)
#pragma unroll
                        for (int n8 = 0; n8 < 8; n8++) {
                            const int n16 = n8 >> 1, sub = n8 & 1;
                            mma16816(acc[mt][n8], a[mt], b[n16][sub], b[n16][sub + 2]);
                        }
                }
            }

#pragma unroll
            for (int mt = 0; mt < 2; mt++) {
                float m0 = runmax[mt][0], m1 = runmax[mt][1];
#pragma unroll
                for (int n8 = 0; n8 < 8; n8++) {
                    m0 = fmaxf(m0, fmaxf(acc[mt][n8][0], acc[mt][n8][1]));
                    m1 = fmaxf(m1, fmaxf(acc[mt][n8][2], acc[mt][n8][3]));
                }
                runmax[mt][0] = m0;
                runmax[mt][1] = m1;
            }
        }

        // segment epilogue: reduce + atomic max into out
        __syncthreads();
#pragma unroll
        for (int mt = 0; mt < 2; mt++) {
#pragma unroll
            for (int hh = 0; hh < 2; hh++) {
                float v = runmax[mt][hh];
                v = fmaxf(v, __shfl_xor_sync(0xffffffffu, v, 1));
                v = fmaxf(v, __shfl_xor_sync(0xffffffffu, v, 2));
                if (tig == 0)
                    red[wn * BM + wm * 32 + mt * 16 + hh * 8 + g] = v;
            }
        }
        __syncthreads();
        if (tid < BM) {
            float v = red[tid];
#pragma unroll
            for (int w = 1; w < 4; w++) v = fmaxf(v, red[w * BM + tid]);
            atomicMax((int*)&out[m * BM + tid], __float_as_int(v));
        }
        __syncthreads();

        t = segEnd;
    }
}

// ---------------------------------------------------------------------------
// launch
// ---------------------------------------------------------------------------
extern "C" void kernel_launch(void* const* d_in, const int* in_sizes, int n_in,
                              void* d_out, int out_size) {
    const float* ex = (const float*)d_in[0];
    const float* ey = (const float*)d_in[1];
    float* out = (float*)d_out;

    cudaFuncSetAttribute(chamfer_kernel, cudaFuncAttributeMaxDynamicSharedMemorySize,
                         SMEM_TOTAL);

    init_out_kernel<<<NROWS / 256, 256>>>(out);
    normalize_kernel<<<NROWS / 8, 256>>>(ex, 0);
    normalize_kernel<<<NROWS / 8, 256>>>(ey, 1);
    chamfer_kernel<<<NCTA, 256, SMEM_TOTAL>>>(out);
}

// round 6
// speedup vs baseline: 1.3195x; 1.3195x over previous
#include <cuda_runtime.h>
#include <cuda_bf16.h>
#include <cstdint>

// ---------------- problem constants ----------------
#define NROWS 8192
#define DDIM  768

// ---------------- GEMM tiling ----------------
#define BM 128             // CTA tile m
#define BN 128             // CTA tile n
#define BK 64              // k per pipeline chunk
#define NKT (DDIM / BK)    // 12 k-chunks
#define NMB (NROWS / BM)   // 64
#define NNB (NROWS / BN)   // 64

// smem: 3-stage ring for A and B, each stage 128 rows x 72 bf16 (144B rows)
#define ROW_B 144
#define STAGE_B (BM * ROW_B)            // 18432
#define OFF_A 0
#define OFF_B (3 * STAGE_B)             // 55296
#define OFF_RED (OFF_B + 3 * STAGE_B)   // 110592
#define SMEM_TOTAL (OFF_RED + 2 * BM * 4)  // +red[2][128] = 111616

// ---------------- device scratch ----------------
__device__ __nv_bfloat16 g_exn[NROWS * DDIM];
__device__ __nv_bfloat16 g_eyn[NROWS * DDIM];

// ---------------- PTX helpers ----------------
__device__ __forceinline__ uint32_t s2u(const void* p) {
    uint32_t a;
    asm("{ .reg .u64 t; cvta.to.shared.u64 t, %1; cvt.u32.u64 %0, t; }" : "=r"(a) : "l"(p));
    return a;
}
__device__ __forceinline__ void cpa16(uint32_t dst, const void* src) {
    asm volatile("cp.async.cg.shared.global [%0], [%1], 16;" :: "r"(dst), "l"(src));
}
__device__ __forceinline__ void cpa_commit() { asm volatile("cp.async.commit_group;"); }
__device__ __forceinline__ void cpa_wait0()  { asm volatile("cp.async.wait_group 0;"); }
__device__ __forceinline__ void cpa_wait1()  { asm volatile("cp.async.wait_group 1;"); }
__device__ __forceinline__ void ldsm4(uint32_t (&r)[4], uint32_t addr) {
    asm volatile("ldmatrix.sync.aligned.m8n8.x4.shared.b16 {%0,%1,%2,%3}, [%4];"
                 : "=r"(r[0]), "=r"(r[1]), "=r"(r[2]), "=r"(r[3]) : "r"(addr));
}
__device__ __forceinline__ void mma16816(float (&c)[4], const uint32_t (&a)[4],
                                         uint32_t b0, uint32_t b1) {
    asm volatile(
        "mma.sync.aligned.m16n8k16.row.col.f32.bf16.bf16.f32 "
        "{%0,%1,%2,%3}, {%4,%5,%6,%7}, {%8,%9}, {%0,%1,%2,%3};"
        : "+f"(c[0]), "+f"(c[1]), "+f"(c[2]), "+f"(c[3])
        : "r"(a[0]), "r"(a[1]), "r"(a[2]), "r"(a[3]), "r"(b0), "r"(b1));
}

// ---------------------------------------------------------------------------
// out init (harness poisons to 0xAA; atomics need 0.0f start)
// ---------------------------------------------------------------------------
__global__ void init_out_kernel(float* __restrict__ out) {
    out[blockIdx.x * 256 + threadIdx.x] = 0.0f;
}

// ---------------------------------------------------------------------------
// Row L2-normalize fp32 -> bf16, warp-per-row (ref: norm = max(||x||,1e-8))
// ---------------------------------------------------------------------------
__global__ __launch_bounds__(256) void normalize_kernel(const float* __restrict__ in, int sel) {
    __nv_bfloat16* outg = sel ? g_eyn : g_exn;
    const int w = threadIdx.x >> 5;
    const int lane = threadIdx.x & 31;
    const int row = blockIdx.x * 8 + w;

    const float4* p = (const float4*)(in + (size_t)row * DDIM);
    float4 v[6];
    float s = 0.f;
#pragma unroll
    for (int j = 0; j < 6; j++) {
        v[j] = p[lane + j * 32];
        s += v[j].x * v[j].x + v[j].y * v[j].y + v[j].z * v[j].z + v[j].w * v[j].w;
    }
#pragma unroll
    for (int o = 16; o; o >>= 1) s += __shfl_xor_sync(0xffffffffu, s, o);
    const float inv = 1.0f / fmaxf(sqrtf(s), 1e-8f);

    uint4* q = (uint4*)(outg + (size_t)row * DDIM);
#pragma unroll
    for (int j = 0; j < 3; j++) {
        const float4 a = v[2 * j], b = v[2 * j + 1];
        __nv_bfloat162 p0 = __floats2bfloat162_rn(a.x * inv, a.y * inv);
        __nv_bfloat162 p1 = __floats2bfloat162_rn(a.z * inv, a.w * inv);
        __nv_bfloat162 p2 = __floats2bfloat162_rn(b.x * inv, b.y * inv);
        __nv_bfloat162 p3 = __floats2bfloat162_rn(b.z * inv, b.w * inv);
        uint4 o;
        o.x = *(uint32_t*)&p0; o.y = *(uint32_t*)&p1;
        o.z = *(uint32_t*)&p2; o.w = *(uint32_t*)&p3;
        q[lane + j * 32] = o;
    }
}

// ---------------------------------------------------------------------------
// Fused GEMM (exn @ eyn^T) + row-max. Streamed A+B, 3-stage ring, 2 CTAs/SM.
// grid = 64x64 tiles; warp grid 4x2 (wm 0..3, wn 0..1); warp tile 32x64.
// ---------------------------------------------------------------------------
__global__ __launch_bounds__(256, 2) void chamfer_kernel(float* __restrict__ out) {
    extern __shared__ char smem[];
    const uint32_t sb = s2u(smem);
    float* red = (float*)(smem + OFF_RED);

    const int tid = threadIdx.x;
    const int lane = tid & 31;
    const int wid = tid >> 5;
    const int wm = wid >> 1;   // 0..3
    const int wn = wid & 1;    // 0..1
    const int g = lane >> 2;
    const int tig = lane & 3;

    const int m = blockIdx.x >> 6;
    const int n = blockIdx.x & 63;
    const __nv_bfloat16* Ag = g_exn + (size_t)m * BM * DDIM;
    const __nv_bfloat16* Bg = g_eyn + (size_t)n * BN * DDIM;

    // chunk loader: 128 rows x 128B for A and B. 2 threads per row; each thread
    // covers 4 contiguous 16B chunks (64B) per matrix.
    const int l_row = tid >> 1;            // 0..127
    const int l_half = (tid & 1) * 64;     // byte offset 0 or 64
    auto issue = [&](int kt) {
        const int s = kt % 3;
        const size_t ko = (size_t)kt * BK + l_half / 2;  // element offset
        const uint32_t da = sb + OFF_A + s * STAGE_B + l_row * ROW_B + l_half;
        const uint32_t db = sb + OFF_B + s * STAGE_B + l_row * ROW_B + l_half;
        const __nv_bfloat16* sa = Ag + (size_t)l_row * DDIM + ko;
        const __nv_bfloat16* sbp = Bg + (size_t)l_row * DDIM + ko;
#pragma unroll
        for (int j = 0; j < 4; j++) {
            cpa16(da + j * 16, sa + j * 8);
            cpa16(db + j * 16, sbp + j * 8);
        }
    };

    issue(0); cpa_commit();
    issue(1); cpa_commit();

    const int lrow = lane & 15;
    const int koff = (lane >> 4) * 16;
    const uint32_t aAddr0 = sb + OFF_A + (wm * 32 + lrow) * ROW_B + koff;
    const uint32_t bAddr0 = sb + OFF_B + (wn * 64 + lrow) * ROW_B + koff;

    float acc[2][8][4];
#pragma unroll
    for (int mt = 0; mt < 2; mt++)
#pragma unroll
        for (int n8 = 0; n8 < 8; n8++)
#pragma unroll
            for (int r = 0; r < 4; r++) acc[mt][n8][r] = 0.f;

    for (int kt = 0; kt < NKT; ++kt) {
        if (kt == NKT - 1) cpa_wait0(); else cpa_wait1();
        __syncthreads();
        if (kt + 2 < NKT) { issue(kt + 2); cpa_commit(); }

        const uint32_t aS = aAddr0 + (kt % 3) * STAGE_B;
        const uint32_t bS = bAddr0 + (kt % 3) * STAGE_B;
#pragma unroll
        for (int kk = 0; kk < 4; ++kk) {
            uint32_t a[2][4], b[4][4];
#pragma unroll
            for (int mt = 0; mt < 2; mt++)
                ldsm4(a[mt], aS + mt * 16 * ROW_B + kk * 32);
#pragma unroll
            for (int n16 = 0; n16 < 4; n16++)
                ldsm4(b[n16], bS + n16 * 16 * ROW_B + kk * 32);
#pragma unroll
            for (int mt = 0; mt < 2; mt++)
#pragma unroll
                for (int n8 = 0; n8 < 8; n8++) {
                    const int n16 = n8 >> 1, sub = n8 & 1;
                    mma16816(acc[mt][n8], a[mt], b[n16][sub], b[n16][sub + 2]);
                }
        }
        __syncthreads();
    }

    // row-max epilogue
    float rm[2][2];
#pragma unroll
    for (int mt = 0; mt < 2; mt++) {
        float m0 = -1e30f, m1 = -1e30f;
#pragma unroll
        for (int n8 = 0; n8 < 8; n8++) {
            m0 = fmaxf(m0, fmaxf(acc[mt][n8][0], acc[mt][n8][1]));
            m1 = fmaxf(m1, fmaxf(acc[mt][n8][2], acc[mt][n8][3]));
        }
        rm[mt][0] = m0; rm[mt][1] = m1;
    }
#pragma unroll
    for (int mt = 0; mt < 2; mt++) {
#pragma unroll
        for (int hh = 0; hh < 2; hh++) {
            float v = rm[mt][hh];
            v = fmaxf(v, __shfl_xor_sync(0xffffffffu, v, 1));
            v = fmaxf(v, __shfl_xor_sync(0xffffffffu, v, 2));
            if (tig == 0)
                red[wn * BM + wm * 32 + mt * 16 + hh * 8 + g] = v;
        }
    }
    __syncthreads();
    if (tid < BM) {
        const float v = fmaxf(red[tid], red[BM + tid]);
        atomicMax((int*)&out[m * BM + tid], __float_as_int(v));
    }
}

// ---------------------------------------------------------------------------
// launch
// ---------------------------------------------------------------------------
extern "C" void kernel_launch(void* const* d_in, const int* in_sizes, int n_in,
                              void* d_out, int out_size) {
    const float* ex = (const float*)d_in[0];
    const float* ey = (const float*)d_in[1];
    float* out = (float*)d_out;

    cudaFuncSetAttribute(chamfer_kernel, cudaFuncAttributeMaxDynamicSharedMemorySize,
                         SMEM_TOTAL);

    init_out_kernel<<<NROWS / 256, 256>>>(out);
    normalize_kernel<<<NROWS / 8, 256>>>(ex, 0);
    normalize_kernel<<<NROWS / 8, 256>>>(ey, 1);
    chamfer_kernel<<<NMB * NNB, 256, SMEM_TOTAL>>>(out);
}

// round 7
// speedup vs baseline: 1.6632x; 1.2605x over previous
#include <cuda_runtime.h>
#include <cuda_bf16.h>
#include <cstdint>

// ---------------- problem constants ----------------
#define NROWS 8192
#define DDIM  768

// ---------------- GEMM tiling ----------------
#define BM 128             // CTA tile m
#define BN 128             // CTA tile n
#define BK 32              // k per pipeline chunk
#define NKT (DDIM / BK)    // 24 k-chunks
#define NMB (NROWS / BM)   // 64
#define NNB (NROWS / BN)   // 64
#define NSTG 5             // pipeline stages per matrix

// smem: 5-stage ring for A and B, each stage 128 rows x 40 bf16 (80B rows)
#define ROW_B 80
#define STAGE_B (BM * ROW_B)              // 10240
#define OFF_A 0
#define OFF_B (NSTG * STAGE_B)            // 51200
#define OFF_RED (OFF_B + NSTG * STAGE_B)  // 102400
#define SMEM_TOTAL (OFF_RED + 2 * BM * 4) // 103424

// ---------------- device scratch ----------------
__device__ __nv_bfloat16 g_exn[NROWS * DDIM];
__device__ __nv_bfloat16 g_eyn[NROWS * DDIM];

// ---------------- PTX helpers ----------------
__device__ __forceinline__ uint32_t s2u(const void* p) {
    uint32_t a;
    asm("{ .reg .u64 t; cvta.to.shared.u64 t, %1; cvt.u32.u64 %0, t; }" : "=r"(a) : "l"(p));
    return a;
}
__device__ __forceinline__ void cpa16(uint32_t dst, const void* src) {
    asm volatile("cp.async.cg.shared.global [%0], [%1], 16;" :: "r"(dst), "l"(src));
}
__device__ __forceinline__ void cpa_commit() { asm volatile("cp.async.commit_group;"); }
__device__ __forceinline__ void cpa_wait3()  { asm volatile("cp.async.wait_group 3;"); }
__device__ __forceinline__ void ldsm4(uint32_t (&r)[4], uint32_t addr) {
    asm volatile("ldmatrix.sync.aligned.m8n8.x4.shared.b16 {%0,%1,%2,%3}, [%4];"
                 : "=r"(r[0]), "=r"(r[1]), "=r"(r[2]), "=r"(r[3]) : "r"(addr));
}
__device__ __forceinline__ void mma16816(float (&c)[4], const uint32_t (&a)[4],
                                         uint32_t b0, uint32_t b1) {
    asm volatile(
        "mma.sync.aligned.m16n8k16.row.col.f32.bf16.bf16.f32 "
        "{%0,%1,%2,%3}, {%4,%5,%6,%7}, {%8,%9}, {%0,%1,%2,%3};"
        : "+f"(c[0]), "+f"(c[1]), "+f"(c[2]), "+f"(c[3])
        : "r"(a[0]), "r"(a[1]), "r"(a[2]), "r"(a[3]), "r"(b0), "r"(b1));
}

// ---------------------------------------------------------------------------
// out init (harness poisons to 0xAA; atomics need 0.0f start)
// ---------------------------------------------------------------------------
__global__ void init_out_kernel(float* __restrict__ out) {
    out[blockIdx.x * 256 + threadIdx.x] = 0.0f;
}

// ---------------------------------------------------------------------------
// Row L2-normalize fp32 -> bf16, warp-per-row (ref: norm = max(||x||,1e-8))
// ---------------------------------------------------------------------------
__global__ __launch_bounds__(256) void normalize_kernel(const float* __restrict__ in, int sel) {
    __nv_bfloat16* outg = sel ? g_eyn : g_exn;
    const int w = threadIdx.x >> 5;
    const int lane = threadIdx.x & 31;
    const int row = blockIdx.x * 8 + w;

    const float4* p = (const float4*)(in + (size_t)row * DDIM);
    float4 v[6];
    float s = 0.f;
#pragma unroll
    for (int j = 0; j < 6; j++) {
        v[j] = p[lane + j * 32];
        s += v[j].x * v[j].x + v[j].y * v[j].y + v[j].z * v[j].z + v[j].w * v[j].w;
    }
#pragma unroll
    for (int o = 16; o; o >>= 1) s += __shfl_xor_sync(0xffffffffu, s, o);
    const float inv = 1.0f / fmaxf(sqrtf(s), 1e-8f);

    uint4* q = (uint4*)(outg + (size_t)row * DDIM);
#pragma unroll
    for (int j = 0; j < 3; j++) {
        const float4 a = v[2 * j], b = v[2 * j + 1];
        __nv_bfloat162 p0 = __floats2bfloat162_rn(a.x * inv, a.y * inv);
        __nv_bfloat162 p1 = __floats2bfloat162_rn(a.z * inv, a.w * inv);
        __nv_bfloat162 p2 = __floats2bfloat162_rn(b.x * inv, b.y * inv);
        __nv_bfloat162 p3 = __floats2bfloat162_rn(b.z * inv, b.w * inv);
        uint4 o;
        o.x = *(uint32_t*)&p0; o.y = *(uint32_t*)&p1;
        o.z = *(uint32_t*)&p2; o.w = *(uint32_t*)&p3;
        q[lane + j * 32] = o;
    }
}

// ---------------------------------------------------------------------------
// Fused GEMM (exn @ eyn^T) + row-max. Streamed A+B, 5-stage ring, 2 CTAs/SM.
// grid = 64x64 tiles; warp grid 4x2 (wm 0..3, wn 0..1); warp tile 32x64.
// ---------------------------------------------------------------------------
__global__ __launch_bounds__(256, 2) void chamfer_kernel(float* __restrict__ out) {
    extern __shared__ char smem[];
    const uint32_t sb = s2u(smem);
    float* red = (float*)(smem + OFF_RED);

    const int tid = threadIdx.x;
    const int lane = tid & 31;
    const int wid = tid >> 5;
    const int wm = wid >> 1;   // 0..3
    const int wn = wid & 1;    // 0..1
    const int g = lane >> 2;
    const int tig = lane & 3;

    const int m = blockIdx.x >> 6;
    const int n = blockIdx.x & 63;
    const __nv_bfloat16* Ag = g_exn + (size_t)m * BM * DDIM;
    const __nv_bfloat16* Bg = g_eyn + (size_t)n * BN * DDIM;

    // chunk loader: 128 rows x 64B for A and B. 2 threads per row; each thread
    // covers 2 contiguous 16B chunks (32B) per matrix.
    const int l_row = tid >> 1;            // 0..127
    const int l_half = (tid & 1) * 32;     // byte offset 0 or 32
    auto issue = [&](int kt) {
        const int s = kt % NSTG;
        const size_t ko = (size_t)kt * BK + l_half / 2;  // element offset
        const uint32_t da = sb + OFF_A + s * STAGE_B + l_row * ROW_B + l_half;
        const uint32_t db = sb + OFF_B + s * STAGE_B + l_row * ROW_B + l_half;
        const __nv_bfloat16* sa = Ag + (size_t)l_row * DDIM + ko;
        const __nv_bfloat16* sbp = Bg + (size_t)l_row * DDIM + ko;
#pragma unroll
        for (int j = 0; j < 2; j++) {
            cpa16(da + j * 16, sa + j * 8);
            cpa16(db + j * 16, sbp + j * 8);
        }
    };

    // prologue: 4 chunks in flight
#pragma unroll
    for (int kt = 0; kt < 4; ++kt) { issue(kt); cpa_commit(); }

    const int lrow = lane & 15;
    const int koff = (lane >> 4) * 16;
    const uint32_t aAddr0 = sb + OFF_A + (wm * 32 + lrow) * ROW_B + koff;
    const uint32_t bAddr0 = sb + OFF_B + (wn * 64 + lrow) * ROW_B + koff;

    float acc[2][8][4];
#pragma unroll
    for (int mt = 0; mt < 2; mt++)
#pragma unroll
        for (int n8 = 0; n8 < 8; n8++)
#pragma unroll
            for (int r = 0; r < 4; r++) acc[mt][n8][r] = 0.f;

    for (int kt = 0; kt < NKT; ++kt) {
        cpa_wait3();          // group kt complete (4 groups pending incl. empties)
        __syncthreads();      // all warps done with stage (kt-1)%5 reads; data visible
        if (kt + 4 < NKT) issue(kt + 4);
        cpa_commit();         // always commit (possibly empty) to keep counts uniform

        const uint32_t aS = aAddr0 + (kt % NSTG) * STAGE_B;
        const uint32_t bS = bAddr0 + (kt % NSTG) * STAGE_B;
#pragma unroll
        for (int kk = 0; kk < 2; ++kk) {
            uint32_t a[2][4], b[4][4];
#pragma unroll
            for (int mt = 0; mt < 2; mt++)
                ldsm4(a[mt], aS + mt * 16 * ROW_B + kk * 32);
#pragma unroll
            for (int n16 = 0; n16 < 4; n16++)
                ldsm4(b[n16], bS + n16 * 16 * ROW_B + kk * 32);
#pragma unroll
            for (int mt = 0; mt < 2; mt++)
#pragma unroll
                for (int n8 = 0; n8 < 8; n8++) {
                    const int n16 = n8 >> 1, sub = n8 & 1;
                    mma16816(acc[mt][n8], a[mt], b[n16][sub], b[n16][sub + 2]);
                }
        }
    }

    // row-max epilogue
    float rm[2][2];
#pragma unroll
    for (int mt = 0; mt < 2; mt++) {
        float m0 = -1e30f, m1 = -1e30f;
#pragma unroll
        for (int n8 = 0; n8 < 8; n8++) {
            m0 = fmaxf(m0, fmaxf(acc[mt][n8][0], acc[mt][n8][1]));
            m1 = fmaxf(m1, fmaxf(acc[mt][n8][2], acc[mt][n8][3]));
        }
        rm[mt][0] = m0; rm[mt][1] = m1;
    }
    __syncthreads();
#pragma unroll
    for (int mt = 0; mt < 2; mt++) {
#pragma unroll
        for (int hh = 0; hh < 2; hh++) {
            float v = rm[mt][hh];
            v = fmaxf(v, __shfl_xor_sync(0xffffffffu, v, 1));
            v = fmaxf(v, __shfl_xor_sync(0xffffffffu, v, 2));
            if (tig == 0)
                red[wn * BM + wm * 32 + mt * 16 + hh * 8 + g] = v;
        }
    }
    __syncthreads();
    if (tid < BM) {
        const float v = fmaxf(red[tid], red[BM + tid]);
        atomicMax((int*)&out[m * BM + tid], __float_as_int(v));
    }
}

// ---------------------------------------------------------------------------
// launch
// ---------------------------------------------------------------------------
extern "C" void kernel_launch(void* const* d_in, const int* in_sizes, int n_in,
                              void* d_out, int out_size) {
    const float* ex = (const float*)d_in[0];
    const float* ey = (const float*)d_in[1];
    float* out = (float*)d_out;

    cudaFuncSetAttribute(chamfer_kernel, cudaFuncAttributeMaxDynamicSharedMemorySize,
                         SMEM_TOTAL);

    init_out_kernel<<<NROWS / 256, 256>>>(out);
    normalize_kernel<<<NROWS / 8, 256>>>(ex, 0);
    normalize_kernel<<<NROWS / 8, 256>>>(ey, 1);
    chamfer_kernel<<<NMB * NNB, 256, SMEM_TOTAL>>>(out);
}